// round 15
// baseline (speedup 1.0000x reference)
#include <cuda_runtime.h>
#include <cuda_fp16.h>
#include <cstdint>

// VQ-VAE vector quantizer on GB300 — dual-pipeline HMMA fp16-split GEMM.
// Two independent 256-thread groups per CTA (named barriers), shared B tiles.
// (Resubmission of round-14 kernel: previous bench aborted on a GB300
//  container/broker failure before any kernel execution.)
//   z_e:      [32, 64, 64, 64] fp32  (B, C, H, W)
//   codebook: [512, 64] fp32
// d_out fp32: z_q (8388608) then indices (131072, stored as float).

#define NUM_K 512
#define DIM_C 64
#define HW    4096
#define N_PTS 131072
#define ZQ_ELEMS 8388608
#define PTS_TILE 128
#define NTILES   (N_PTS / PTS_TILE)
#define GRID_MAIN 148
#define NTHREADS 512
#define THRESH 6e-5f

// smem offsets from 1024-aligned base
#define OFF_BH   0          // B_hi 512x64 fp16 SW128 : 65536
#define OFF_BL   65536      // B_lo                    : 65536
#define OFF_CSQ  131072     // 512 f : 2048
#define OFF_GRP  133120     // per-group blocks
#define GRP_STRIDE 40960
// per-group offsets (relative to group base)
#define G_AH   0            // A_hi [64c][128p] fp16 chunk-swizzled : 16384
#define G_AL   16384        // A_lo : 16384
#define G_RD   32768        // 128x2 f : 1024
#define G_R2   33792        // 128x2 f : 1024
#define G_RK   34816        // 128x2 i : 1024
#define G_BK   35840        // 128 i : 512
#define G_FLG  36352        // cnt + 128 i (padded to 1024)
#define G_ZSC  37376        // 8 warps x 64 f : 2048
#define SMEM_BYTES (OFF_GRP + 2 * GRP_STRIDE + 1024)

#define SWZ128(o) ((o) ^ ((((unsigned)(o)) >> 3) & 0x70u))
#define GROUP_BAR(g) asm volatile("bar.sync %0, 256;" :: "r"((g) + 1) : "memory")

__device__ __forceinline__ uint32_t smem_u32(const void* p) {
    uint32_t a;
    asm("{ .reg .u64 t; cvta.to.shared.u64 t, %1; cvt.u32.u64 %0, t; }" : "=r"(a) : "l"(p));
    return a;
}
__device__ __forceinline__ void ldsm_x4_t(uint32_t* a, uint32_t addr) {
    asm volatile("ldmatrix.sync.aligned.m8n8.x4.trans.shared.b16 {%0,%1,%2,%3}, [%4];"
        : "=r"(a[0]), "=r"(a[1]), "=r"(a[2]), "=r"(a[3]) : "r"(addr));
}
__device__ __forceinline__ void ldsm_x2(uint32_t* a, uint32_t addr) {
    asm volatile("ldmatrix.sync.aligned.m8n8.x2.shared.b16 {%0,%1}, [%2];"
        : "=r"(a[0]), "=r"(a[1]) : "r"(addr));
}
__device__ __forceinline__ void mma16816(float* c, const uint32_t* a, const uint32_t* b) {
    asm volatile("mma.sync.aligned.m16n8k16.row.col.f32.f16.f16.f32 "
        "{%0,%1,%2,%3}, {%4,%5,%6,%7}, {%8,%9}, {%0,%1,%2,%3};"
        : "+f"(c[0]), "+f"(c[1]), "+f"(c[2]), "+f"(c[3])
        : "r"(a[0]), "r"(a[1]), "r"(a[2]), "r"(a[3]), "r"(b[0]), "r"(b[1]));
}
// A tile [channel][point] fp16 rows of 256B; 16B point-chunks XOR-swizzled by
// channel. ldmatrix.trans gives standard m16n8k16 A-frag register layout.
__device__ __forceinline__ uint32_t addr_At(uint32_t tb, int m0, int k0, int lane) {
    int i = lane & 7, j = lane >> 3;
    int c = k0 + i + ((j >> 1) << 3);
    int m = m0 + ((j & 1) << 3);
    return tb + (uint32_t)c * 256u + (uint32_t)((((m >> 3) ^ (c & 15)) & 15) << 4);
}
// B tile [code][channel] fp16, 128B rows, SW128.
__device__ __forceinline__ uint32_t addr_B(uint32_t tb, int n0, int k0, int lane) {
    int r = lane & 7, sel = (lane >> 3) & 1;
    uint32_t off = (uint32_t)((n0 + r) * 128 + (k0 + sel * 8) * 2);
    return tb + SWZ128(off);
}

// ---------------------------------------------------------------------------
__global__ __launch_bounds__(NTHREADS, 1) void vq_mma_kernel(
    const float* __restrict__ z,
    const float* __restrict__ cb,
    float* __restrict__ out,
    int write_idx)
{
    extern __shared__ char smraw[];
    uint32_t sm0 = smem_u32(smraw);
    uint32_t base = (sm0 + 1023u) & ~1023u;
    char* sm = smraw + (base - sm0);

    float* sCSQ = reinterpret_cast<float*>(sm + OFF_CSQ);

    const int tid  = threadIdx.x;
    const int g    = tid >> 8;            // group 0/1
    const int ltid = tid & 255;           // thread within group
    const int lw   = ltid >> 5, lane = ltid & 31;
    const int qr   = lane >> 2, qc = lane & 3;
    const int mgrp = lw & 3, ngrp = lw >> 2;   // 4 M-warps x 2 N-warps
    const int mbase = mgrp * 32;

    const uint32_t gb = base + OFF_GRP + (uint32_t)g * GRP_STRIDE;
    char* gsm = sm + OFF_GRP + g * GRP_STRIDE;
    float* sRD  = reinterpret_cast<float*>(gsm + G_RD);
    float* sR2  = reinterpret_cast<float*>(gsm + G_R2);
    int*   sRK  = reinterpret_cast<int*>  (gsm + G_RK);
    int*   sBK  = reinterpret_cast<int*>  (gsm + G_BK);
    int*   sFlagCnt  = reinterpret_cast<int*>(gsm + G_FLG);
    int*   sFlagList = sFlagCnt + 1;
    float* sZC  = reinterpret_cast<float*>(gsm + G_ZSC);

    // ---- One-time prep (all 512 threads): split codebook + csq. ----
    {
        const float2* cb2 = reinterpret_cast<const float2*>(cb);
        for (int i = tid; i < NUM_K * DIM_C / 2; i += NTHREADS) {   // half2 units
            float2 v = __ldg(&cb2[i]);
            float a = v.x * 512.0f, bb = v.y * 512.0f;
            __half ha = __float2half_rn(a), hb = __float2half_rn(bb);
            __half la = __float2half_rn(a - __half2float(ha));
            __half lb = __float2half_rn(bb - __half2float(hb));
            uint32_t boff = (uint32_t)i * 4u;
            *reinterpret_cast<__half2*>(sm + OFF_BH + SWZ128(boff)) = __halves2half2(ha, hb);
            *reinterpret_cast<__half2*>(sm + OFF_BL + SWZ128(boff)) = __halves2half2(la, lb);
        }
        if (tid < NUM_K) {
            int k = tid;
            const float4* row = reinterpret_cast<const float4*>(cb + k * DIM_C);
            float s0 = 0.f, s1 = 0.f, s2 = 0.f, s3 = 0.f;
            #pragma unroll
            for (int j = 0; j < 16; j++) {
                float4 v = __ldg(&row[j]);
                s0 = fmaf(v.x, v.x, s0); s1 = fmaf(v.y, v.y, s1);
                s2 = fmaf(v.z, v.z, s2); s3 = fmaf(v.w, v.w, s3);
            }
            sCSQ[k] = (s0 + s1) + (s2 + s3);
        }
    }
    __syncthreads();   // last CTA-wide barrier; groups now independent

    const int nworkers = gridDim.x * 2;
    for (int t = blockIdx.x * 2 + g; t < NTILES; t += nworkers) {
        const int n0t = t * PTS_TILE, b = n0t >> 12, hw0 = n0t & 4095;
        const float* zb = z + (size_t)b * (DIM_C * HW) + hw0;

        // ---- Stage + build A_hi/A_lo (global -> fp16 split), 256 thr. ----
        #pragma unroll 4
        for (int j = 0; j < 8; j++) {
            int i = ltid + j * 256;               // 2048 float4 total
            int c = i >> 5, p4 = (i & 31) * 4;
            float4 v = *reinterpret_cast<const float4*>(zb + (size_t)c * HW + p4);
            __half h0 = __float2half_rn(v.x), h1 = __float2half_rn(v.y);
            __half h2 = __float2half_rn(v.z), h3 = __float2half_rn(v.w);
            __half l0 = __float2half_rn(v.x - __half2float(h0));
            __half l1 = __float2half_rn(v.y - __half2float(h1));
            __half l2 = __float2half_rn(v.z - __half2float(h2));
            __half l3 = __float2half_rn(v.w - __half2float(h3));
            uint32_t aoff = (uint32_t)c * 256u
                          + (uint32_t)(((((p4 >> 3) ^ c) & 15) << 4))
                          + (uint32_t)((p4 & 7) * 2);
            __half2 hi01 = __halves2half2(h0, h1), hi23 = __halves2half2(h2, h3);
            __half2 lo01 = __halves2half2(l0, l1), lo23 = __halves2half2(l2, l3);
            uint2 hw_, lw_;
            hw_.x = *reinterpret_cast<uint32_t*>(&hi01);
            hw_.y = *reinterpret_cast<uint32_t*>(&hi23);
            lw_.x = *reinterpret_cast<uint32_t*>(&lo01);
            lw_.y = *reinterpret_cast<uint32_t*>(&lo23);
            *reinterpret_cast<uint2*>(gsm + G_AH + aoff) = hw_;
            *reinterpret_cast<uint2*>(gsm + G_AL + aoff) = lw_;
        }
        if (ltid == 0) *sFlagCnt = 0;
        GROUP_BAR(g);

        float best[4], sec[4]; int bk[4];
        #pragma unroll
        for (int i = 0; i < 4; i++) { best[i] = 3.402823466e38f; sec[i] = 3.402823466e38f; bk[i] = 0; }

        // ---- GEMM: warp covers 32 pts x 256 codes, N-chunks of 32. ----
        #pragma unroll 1
        for (int cc = 0; cc < 8; cc++) {
            float acc[2][4][4];
            #pragma unroll
            for (int mt = 0; mt < 2; mt++)
                #pragma unroll
                for (int nt = 0; nt < 4; nt++)
                    #pragma unroll
                    for (int r = 0; r < 4; r++) acc[mt][nt][r] = 0.0f;

            const int nb = ngrp * 256 + cc * 32;
            #pragma unroll
            for (int ks = 0; ks < 4; ks++) {
                const int k0 = ks * 16;
                uint32_t ah[2][4], al[2][4], bh[4][2], bl[4][2];
                #pragma unroll
                for (int mt = 0; mt < 2; mt++) {
                    ldsm_x4_t(ah[mt], addr_At(gb + G_AH, mbase + mt * 16, k0, lane));
                    ldsm_x4_t(al[mt], addr_At(gb + G_AL, mbase + mt * 16, k0, lane));
                }
                #pragma unroll
                for (int nt = 0; nt < 4; nt++) {
                    ldsm_x2(bh[nt], addr_B(base + OFF_BH, nb + nt * 8, k0, lane));
                    ldsm_x2(bl[nt], addr_B(base + OFF_BL, nb + nt * 8, k0, lane));
                }
                #pragma unroll
                for (int mt = 0; mt < 2; mt++)
                    #pragma unroll
                    for (int nt = 0; nt < 4; nt++) mma16816(acc[mt][nt], ah[mt], bh[nt]);
                #pragma unroll
                for (int mt = 0; mt < 2; mt++)
                    #pragma unroll
                    for (int nt = 0; nt < 4; nt++) mma16816(acc[mt][nt], ah[mt], bl[nt]);
                #pragma unroll
                for (int mt = 0; mt < 2; mt++)
                    #pragma unroll
                    for (int nt = 0; nt < 4; nt++) mma16816(acc[mt][nt], al[mt], bh[nt]);
            }

            // ---- Fold in SCORE space: s = csq[k] - D*2^-8 (zsq cancels). ----
            #pragma unroll
            for (int mt = 0; mt < 2; mt++) {
                #pragma unroll
                for (int nt = 0; nt < 4; nt++) {
                    int n0 = nb + nt * 8 + 2 * qc;
                    float2 cs = *reinterpret_cast<const float2*>(sCSQ + n0);
                    #pragma unroll
                    for (int h = 0; h < 2; h++) {       // 0: rows qr, 1: rows qr+8
                        int s = mt * 2 + h;
                        float da = fmaf(acc[mt][nt][2 * h],     -0.00390625f, cs.x);
                        float db = fmaf(acc[mt][nt][2 * h + 1], -0.00390625f, cs.y);
                        if (da < best[s]) { sec[s] = best[s]; best[s] = da; bk[s] = n0; }
                        else if (da < sec[s]) sec[s] = da;
                        if (db < best[s]) { sec[s] = best[s]; best[s] = db; bk[s] = n0 + 1; }
                        else if (db < sec[s]) sec[s] = db;
                    }
                }
            }
        }

        // ---- Quad reduce (lanes sharing qr): merge (d1,k1,d2) triples. ----
        #pragma unroll
        for (int i = 0; i < 4; i++) {
            float d1 = best[i], d2 = sec[i]; int k1 = bk[i];
            #pragma unroll
            for (int ofs = 1; ofs <= 2; ofs <<= 1) {
                float od1 = __shfl_xor_sync(0xffffffffu, d1, ofs);
                int   ok1 = __shfl_xor_sync(0xffffffffu, k1, ofs);
                float od2 = __shfl_xor_sync(0xffffffffu, d2, ofs);
                if (od1 < d1 || (od1 == d1 && ok1 < k1)) {
                    d2 = fminf(od2, d1); d1 = od1; k1 = ok1;
                } else {
                    d2 = fminf(d2, od1);
                }
            }
            if (qc == 0) {
                int row = mbase + (i >> 1) * 16 + qr + (i & 1) * 8;
                sRD[row * 2 + ngrp] = d1;
                sRK[row * 2 + ngrp] = k1;
                sR2[row * 2 + ngrp] = d2;
            }
        }
        GROUP_BAR(g);

        // ---- Merge 2 N-halves (k-ascending); flag near-ties. ----
        if (ltid < PTS_TILE) {
            float d1 = sRD[ltid * 2], d2 = sR2[ltid * 2]; int k1 = sRK[ltid * 2];
            float od1 = sRD[ltid * 2 + 1], od2 = sR2[ltid * 2 + 1];
            int   ok1 = sRK[ltid * 2 + 1];
            if (od1 < d1) { d2 = fminf(od2, d1); d1 = od1; k1 = ok1; }
            else          { d2 = fminf(d2, od1); }
            sBK[ltid] = k1;
            if (d2 - d1 <= THRESH) {
                int pos = atomicAdd(sFlagCnt, 1);
                sFlagList[pos] = ltid;
            }
        }
        GROUP_BAR(g);

        // ---- Exact fp32 rescore of flagged points (reference formula). ----
        {
            int cnt = *sFlagCnt;
            const float4* cbg = reinterpret_cast<const float4*>(cb);
            float* zs_w = sZC + lw * 64;
            for (int f = lw; f < cnt; f += 8) {
                int p = sFlagList[f];
                float a0 = __ldg(&zb[(size_t)lane * HW + p]);
                float a1 = __ldg(&zb[(size_t)(lane + 32) * HW + p]);
                zs_w[lane] = a0; zs_w[lane + 32] = a1;
                __syncwarp();
                double zs = (double)a0 * a0 + (double)a1 * a1;
                #pragma unroll
                for (int ofs = 16; ofs >= 1; ofs >>= 1)
                    zs += __shfl_xor_sync(0xffffffffu, zs, ofs);
                float zsqp = (float)zs;

                float bd = 3.402823466e38f; int bkk = 0;
                for (int i = 0; i < 16; i++) {
                    int k = lane * 16 + i;
                    float d0 = 0.f, d1 = 0.f, d2 = 0.f, d3 = 0.f;
                    #pragma unroll
                    for (int j = 0; j < 16; j++) {
                        float4 cv = __ldg(&cbg[k * 16 + j]);
                        d0 = fmaf(zs_w[4 * j + 0], cv.x, d0);
                        d1 = fmaf(zs_w[4 * j + 1], cv.y, d1);
                        d2 = fmaf(zs_w[4 * j + 2], cv.z, d2);
                        d3 = fmaf(zs_w[4 * j + 3], cv.w, d3);
                    }
                    float dot = (d0 + d1) + (d2 + d3);
                    float d = __fadd_rn(__fadd_rn(zsqp, sCSQ[k]), -2.0f * dot);
                    if (d < bd) { bd = d; bkk = k; }
                }
                #pragma unroll
                for (int ofs = 1; ofs < 32; ofs <<= 1) {
                    float od = __shfl_xor_sync(0xffffffffu, bd, ofs);
                    int   ok = __shfl_xor_sync(0xffffffffu, bkk, ofs);
                    if (od < bd || (od == bd && ok < bkk)) { bd = od; bkk = ok; }
                }
                if (lane == 0) sBK[p] = bkk;
                __syncwarp();
            }
        }
        GROUP_BAR(g);

        // ---- Writeback. ----
        if (ltid < PTS_TILE) {
            int bkk = sBK[ltid];
            float* op = out + (size_t)b * (DIM_C * HW) + hw0 + ltid;
            const float4* crow = reinterpret_cast<const float4*>(cb + (size_t)bkk * DIM_C);
            #pragma unroll
            for (int i = 0; i < 16; i++) {
                float4 v = __ldg(&crow[i]);
                op[(size_t)(4 * i + 0) * HW] = v.x;
                op[(size_t)(4 * i + 1) * HW] = v.y;
                op[(size_t)(4 * i + 2) * HW] = v.z;
                op[(size_t)(4 * i + 3) * HW] = v.w;
            }
            if (write_idx) out[ZQ_ELEMS + n0t + ltid] = (float)bkk;
        }
        GROUP_BAR(g);   // sBK/sRD safe to overwrite next iteration
    }
}

// ---------------------------------------------------------------------------
extern "C" void kernel_launch(void* const* d_in, const int* in_sizes, int n_in,
                              void* d_out, int out_size) {
    const float* z  = (const float*)d_in[0];
    const float* cb = (const float*)d_in[1];
    float* out = (float*)d_out;

    int write_idx = (out_size >= ZQ_ELEMS + N_PTS) ? 1 : 0;

    cudaFuncSetAttribute(vq_mma_kernel,
                         cudaFuncAttributeMaxDynamicSharedMemorySize, SMEM_BYTES);

    vq_mma_kernel<<<GRID_MAIN, NTHREADS, SMEM_BYTES>>>(z, cb, out, write_idx);
}